// round 16
// baseline (speedup 1.0000x reference)
#include <cuda_runtime.h>
#include <cuda_fp16.h>

// B=4, N=256, M=256, D=64. TWO CTAs per (b,i) tile (h = bid&1 owns rows 128h..128h+128).
// 128 threads = 4 warps; warp owns 32 rows (two m16 tiles, 4 MMAs per ldmatrix.x4).
// __launch_bounds__(128,2): 2 CTAs/SM, each warp keeps the full ~255-reg ILP budget.
// Fused algebra (in-CTA): Wg[n][k]=(Wk^T Wq)[k][n]/8, W2[n][k]=(Wo Wv)[n][k],
//   h1=Wk^T bq/8, h2=Wq^T bk/8, wbv=Wo bv, s0=bk.bq/8  (t2/t3 = scalar dots vs sX).
// G = X*Wg ; S = G*X^T + t2_a + t3_c ; P = relu(S) ; U = P*X (trans-ldmatrix on sX)
// out = U*inv*W2^T + cden*wbv + bo + x ; LayerNorm.

#define QS 72
#define WS 72
#define OX   0
#define OWQ  18432
#define OWK  23040
#define OWV  27648
#define OWO  32256
#define OWG  36864
#define OW2  41472
#define OEND 46080   // halves; floats after

__device__ __forceinline__ void mma16(float4& d, const unsigned a[4], unsigned b0, unsigned b1) {
    asm("mma.sync.aligned.m16n8k16.row.col.f32.f16.f16.f32 "
        "{%0,%1,%2,%3},{%4,%5,%6,%7},{%8,%9},{%0,%1,%2,%3};"
        : "+f"(d.x), "+f"(d.y), "+f"(d.z), "+f"(d.w)
        : "r"(a[0]), "r"(a[1]), "r"(a[2]), "r"(a[3]), "r"(b0), "r"(b1));
}
__device__ __forceinline__ void ldsm4(unsigned& r0, unsigned& r1, unsigned& r2, unsigned& r3,
                                      const __half* p) {
    unsigned a = (unsigned)__cvta_generic_to_shared(p);
    asm volatile("ldmatrix.sync.aligned.m8n8.x4.shared.b16 {%0,%1,%2,%3},[%4];"
                 : "=r"(r0), "=r"(r1), "=r"(r2), "=r"(r3) : "r"(a));
}
__device__ __forceinline__ void ldsm4t(unsigned& r0, unsigned& r1, unsigned& r2, unsigned& r3,
                                       const __half* p) {
    unsigned a = (unsigned)__cvta_generic_to_shared(p);
    asm volatile("ldmatrix.sync.aligned.m8n8.x4.trans.shared.b16 {%0,%1,%2,%3},[%4];"
                 : "=r"(r0), "=r"(r1), "=r"(r2), "=r"(r3) : "r"(a));
}
__device__ __forceinline__ unsigned pack2(float lo, float hi) {
    __half2 h = __floats2half2_rn(lo, hi);
    return *reinterpret_cast<unsigned*>(&h);
}
// 128-thread weight stage: thread -> row tid/2, 32-col half-row.
__device__ __forceinline__ void stageW128(const float* __restrict__ W, __half* dst, int tid) {
    const int f  = tid >> 1;
    const int e0 = (tid & 1) * 32;
    #pragma unroll
    for (int q = 0; q < 4; q++) {
        float4 p0 = *(const float4*)(W + f * 64 + e0 + 8 * q);
        float4 p1 = *(const float4*)(W + f * 64 + e0 + 8 * q + 4);
        unsigned u[4] = {pack2(p0.x, p0.y), pack2(p0.z, p0.w),
                         pack2(p1.x, p1.y), pack2(p1.z, p1.w)};
        *(uint4*)&dst[f * WS + e0 + 8 * q] = *(uint4*)u;
    }
}

__global__ void __launch_bounds__(128, 2)
pair_attn_v13(const float* __restrict__ x_all,
              const float* __restrict__ Wq, const float* __restrict__ bq,
              const float* __restrict__ Wk, const float* __restrict__ bk,
              const float* __restrict__ Wv, const float* __restrict__ bv,
              const float* __restrict__ Wo, const float* __restrict__ bo,
              const float* __restrict__ lng, const float* __restrict__ lnb,
              float* __restrict__ out_all)
{
    extern __shared__ __half sm[];
    __half* sX  = sm + OX;
    __half* sWg = sm + OWG;
    __half* sW2 = sm + OW2;
    float*  fs   = (float*)(sm + OEND);
    float*  t2s  = fs;          // [256]
    float*  t3s  = fs + 256;    // [256]
    float*  h1s  = fs + 512;    // [64]
    float*  h2s  = fs + 576;    // [64]
    float*  swbv = fs + 640;    // [64]
    float*  s0s  = fs + 704;    // [1]

    const int tid  = threadIdx.x;
    const int lane = tid & 31;
    const int wrp  = tid >> 5;          // 0..3
    const int g    = lane >> 2;
    const int t    = lane & 3;
    const int half = blockIdx.x & 1;
    const int R0   = half * 128 + wrp * 32;   // global rows owned by this warp
    const int lro  = ((lane >> 4) & 1) * 8 + (lane & 7);  // non-trans B / trans A
    const int lco  = ((lane >> 3) & 1) * 8;
    const int vro  = ((lane >> 3) & 1) * 8 + (lane & 7);  // trans B
    const int vco  = ((lane >> 4) & 1) * 8;
    const int aro  = lane & 15;                           // non-trans A
    const int aco  = ((lane >> 4) & 1) * 8;

    const float* xg = x_all   + (size_t)(blockIdx.x >> 1) * 16384;
    float*       og = out_all + (size_t)(blockIdx.x >> 1) * 16384;

    // ================= Phase A: staging =================
    {
        const float4* x4 = (const float4*)xg;
        #pragma unroll
        for (int i = 0; i < 32; i++) {
            int idx = tid + 128 * i;
            int row = idx >> 4, c4 = idx & 15;
            float4 v = x4[idx];
            *(uint2*)&sX[row * QS + c4 * 4] = make_uint2(pack2(v.x, v.y), pack2(v.z, v.w));
        }
        stageW128(Wq, sm + OWQ, tid);
        stageW128(Wk, sm + OWK, tid);
        stageW128(Wv, sm + OWV, tid);
        stageW128(Wo, sm + OWO, tid);
        if (tid < 64) {
            float a0 = 0.f, a1 = 0.f, a2 = 0.f, a3 = 0.f, wv = 0.f;
            #pragma unroll
            for (int j = 0; j < 64; j += 4) {
                a0 = fmaf(__ldg(bq + j + 0), __ldg(Wk + (j + 0) * 64 + tid), a0);
                a1 = fmaf(__ldg(bq + j + 1), __ldg(Wk + (j + 1) * 64 + tid), a1);
                a2 = fmaf(__ldg(bq + j + 2), __ldg(Wk + (j + 2) * 64 + tid), a2);
                a3 = fmaf(__ldg(bq + j + 3), __ldg(Wk + (j + 3) * 64 + tid), a3);
                float4 w = __ldg((const float4*)&Wo[tid * 64 + j]);
                float4 b = __ldg((const float4*)&bv[j]);
                wv += w.x * b.x + w.y * b.y + w.z * b.z + w.w * b.w;
            }
            h1s[tid] = ((a0 + a1) + (a2 + a3)) * 0.125f;
            swbv[tid] = wv;
        } else {
            int i = tid - 64;
            float a0 = 0.f, a1 = 0.f, a2 = 0.f, a3 = 0.f;
            #pragma unroll
            for (int j = 0; j < 64; j += 4) {
                a0 = fmaf(__ldg(bk + j + 0), __ldg(Wq + (j + 0) * 64 + i), a0);
                a1 = fmaf(__ldg(bk + j + 1), __ldg(Wq + (j + 1) * 64 + i), a1);
                a2 = fmaf(__ldg(bk + j + 2), __ldg(Wq + (j + 2) * 64 + i), a2);
                a3 = fmaf(__ldg(bk + j + 3), __ldg(Wq + (j + 3) * 64 + i), a3);
            }
            h2s[i] = ((a0 + a1) + (a2 + a3)) * 0.125f;
            if (tid == 127) {
                float s = 0.f;
                #pragma unroll
                for (int j = 0; j < 64; j++) s = fmaf(__ldg(bk + j), __ldg(bq + j), s);
                s0s[0] = s * 0.125f;
            }
        }
    }
    __syncthreads();   // B1

    // ================= Phase B: Wg / W2 via MMA (each warp: one m-tile of each) ======
    {
        const int m0 = 16 * wrp;
        // Wg[m][k'] = sum_j Wq[j][m]*Wk[j][k'] /8  (A = Wq^T trans-A map, B = Wk^T)
        float4 dW[8];
        #pragma unroll
        for (int nt = 0; nt < 8; nt++) dW[nt] = make_float4(0.f, 0.f, 0.f, 0.f);
        #pragma unroll
        for (int kt = 0; kt < 4; kt++) {
            unsigned a[4];
            ldsm4t(a[0], a[1], a[2], a[3], &sm[OWQ + (16 * kt + lro) * WS + m0 + lco]);
            #pragma unroll
            for (int jj = 0; jj < 4; jj++) {
                unsigned b0, b1, b2, b3;
                ldsm4t(b0, b1, b2, b3, &sm[OWK + (16 * kt + vro) * WS + 16 * jj + vco]);
                mma16(dW[2*jj],   a, b0, b1);
                mma16(dW[2*jj+1], a, b2, b3);
            }
        }
        #pragma unroll
        for (int nt = 0; nt < 8; nt++) {
            *(unsigned*)&sWg[(m0 + g) * WS + 8 * nt + 2 * t]     = pack2(dW[nt].x * 0.125f, dW[nt].y * 0.125f);
            *(unsigned*)&sWg[(m0 + 8 + g) * WS + 8 * nt + 2 * t] = pack2(dW[nt].z * 0.125f, dW[nt].w * 0.125f);
        }
        // W2[m][k'] = sum_j Wo[m][j]*Wv[j][k']  (A = Wo non-trans, B = Wv^T)
        #pragma unroll
        for (int nt = 0; nt < 8; nt++) dW[nt] = make_float4(0.f, 0.f, 0.f, 0.f);
        #pragma unroll
        for (int kt = 0; kt < 4; kt++) {
            unsigned a[4];
            ldsm4(a[0], a[1], a[2], a[3], &sm[OWO + (m0 + aro) * WS + 16 * kt + aco]);
            #pragma unroll
            for (int jj = 0; jj < 4; jj++) {
                unsigned b0, b1, b2, b3;
                ldsm4t(b0, b1, b2, b3, &sm[OWV + (16 * kt + vro) * WS + 16 * jj + vco]);
                mma16(dW[2*jj],   a, b0, b1);
                mma16(dW[2*jj+1], a, b2, b3);
            }
        }
        #pragma unroll
        for (int nt = 0; nt < 8; nt++) {
            *(unsigned*)&sW2[(m0 + g) * WS + 8 * nt + 2 * t]     = pack2(dW[nt].x, dW[nt].y);
            *(unsigned*)&sW2[(m0 + 8 + g) * WS + 8 * nt + 2 * t] = pack2(dW[nt].z, dW[nt].w);
        }
    }
    // ---- t2/t3 scalar dots (2 rows per thread, off the MMA path) ----
    {
        const float s0v = s0s[0];
        #pragma unroll
        for (int rr = 0; rr < 2; rr++) {
            int r = 2 * tid + rr;
            float a = 0.f, b = 0.f;
            #pragma unroll
            for (int i = 0; i < 8; i++) {
                uint4 u = *(const uint4*)&sX[r * QS + i * 8];
                unsigned uu[4] = {u.x, u.y, u.z, u.w};
                #pragma unroll
                for (int q = 0; q < 4; q++) {
                    float2 f = __half22float2(*(__half2*)&uu[q]);
                    int c = i * 8 + q * 2;
                    a = fmaf(f.x, h1s[c], fmaf(f.y, h1s[c + 1], a));
                    b = fmaf(f.x, h2s[c], fmaf(f.y, h2s[c + 1], b));
                }
            }
            t2s[r] = a;
            t3s[r] = b + s0v;
        }
    }
    __syncthreads();   // B2

    // ================= Phase C: G = X*Wg for own 32 rows =================
    unsigned ga[2][4][4];
    {
        unsigned xa[2][4][4];
        #pragma unroll
        for (int mt = 0; mt < 2; mt++)
            #pragma unroll
            for (int kt = 0; kt < 4; kt++)
                ldsm4(xa[mt][kt][0], xa[mt][kt][1], xa[mt][kt][2], xa[mt][kt][3],
                      &sX[(R0 + 16 * mt + aro) * QS + 16 * kt + aco]);
        float4 d0[8], d1[8];
        #pragma unroll
        for (int nt = 0; nt < 8; nt++) {
            d0[nt] = make_float4(0.f, 0.f, 0.f, 0.f);
            d1[nt] = d0[nt];
        }
        #pragma unroll
        for (int kt = 0; kt < 4; kt++)
            #pragma unroll
            for (int j = 0; j < 4; j++) {
                unsigned b0, b1, b2, b3;
                ldsm4(b0, b1, b2, b3, &sWg[(16 * j + lro) * WS + 16 * kt + lco]);
                mma16(d0[2*j],   xa[0][kt], b0, b1);
                mma16(d0[2*j+1], xa[0][kt], b2, b3);
                mma16(d1[2*j],   xa[1][kt], b0, b1);
                mma16(d1[2*j+1], xa[1][kt], b2, b3);
            }
        #pragma unroll
        for (int kt = 0; kt < 4; kt++) {
            ga[0][kt][0] = pack2(d0[2*kt].x,   d0[2*kt].y);
            ga[0][kt][1] = pack2(d0[2*kt].z,   d0[2*kt].w);
            ga[0][kt][2] = pack2(d0[2*kt+1].x, d0[2*kt+1].y);
            ga[0][kt][3] = pack2(d0[2*kt+1].z, d0[2*kt+1].w);
            ga[1][kt][0] = pack2(d1[2*kt].x,   d1[2*kt].y);
            ga[1][kt][1] = pack2(d1[2*kt].z,   d1[2*kt].w);
            ga[1][kt][2] = pack2(d1[2*kt+1].x, d1[2*kt+1].y);
            ga[1][kt][3] = pack2(d1[2*kt+1].z, d1[2*kt+1].w);
        }
    }
    const float t2A0 = t2s[R0 + g],      t2B0 = t2s[R0 + 8 + g];
    const float t2A1 = t2s[R0 + 16 + g], t2B1 = t2s[R0 + 24 + g];

    // ================= Mainloop =================
    float4 ctx[2][8];
    #pragma unroll
    for (int mt = 0; mt < 2; mt++)
        #pragma unroll
        for (int nt = 0; nt < 8; nt++) ctx[mt][nt] = make_float4(0.f, 0.f, 0.f, 0.f);
    float den[2][2] = {{0.f, 0.f}, {0.f, 0.f}};

    #pragma unroll 2
    for (int cb = 0; cb < 16; cb++) {
        const float2 tcA = *(const float2*)&t3s[16 * cb + 2 * t];
        const float2 tcB = *(const float2*)&t3s[16 * cb + 8 + 2 * t];
        float4 s[2][2];
        s[0][0] = make_float4(0.f, 0.f, 0.f, 0.f);
        s[0][1] = s[0][0]; s[1][0] = s[0][0]; s[1][1] = s[0][0];
        #pragma unroll
        for (int kt = 0; kt < 4; kt++) {
            unsigned q0, q1, q2, q3;
            ldsm4(q0, q1, q2, q3, &sX[(16 * cb + lro) * QS + 16 * kt + lco]);
            mma16(s[0][0], ga[0][kt], q0, q1);
            mma16(s[0][1], ga[0][kt], q2, q3);
            mma16(s[1][0], ga[1][kt], q0, q1);
            mma16(s[1][1], ga[1][kt], q2, q3);
        }
        unsigned pa[2][4];
        #pragma unroll
        for (int mt = 0; mt < 2; mt++) {
            const float tA = mt ? t2A1 : t2A0, tB = mt ? t2B1 : t2B0;
            float ex = fmaxf(s[mt][0].x + tA + tcA.x, 0.f), ey = fmaxf(s[mt][0].y + tA + tcA.y, 0.f);
            float ez = fmaxf(s[mt][0].z + tB + tcA.x, 0.f), ew = fmaxf(s[mt][0].w + tB + tcA.y, 0.f);
            float ox = fmaxf(s[mt][1].x + tA + tcB.x, 0.f), oy = fmaxf(s[mt][1].y + tA + tcB.y, 0.f);
            float oz = fmaxf(s[mt][1].z + tB + tcB.x, 0.f), ow = fmaxf(s[mt][1].w + tB + tcB.y, 0.f);
            den[mt][0] += (ex + ey) + (ox + oy);
            den[mt][1] += (ez + ew) + (oz + ow);
            pa[mt][0] = pack2(ex, ey); pa[mt][1] = pack2(ez, ew);
            pa[mt][2] = pack2(ox, oy); pa[mt][3] = pack2(oz, ow);
        }
        #pragma unroll
        for (int j = 0; j < 4; j++) {
            unsigned v0, v1, v2, v3;
            ldsm4t(v0, v1, v2, v3, &sX[(16 * cb + vro) * QS + 16 * j + vco]);
            mma16(ctx[0][2*j],   pa[0], v0, v1);
            mma16(ctx[0][2*j+1], pa[0], v2, v3);
            mma16(ctx[1][2*j],   pa[1], v0, v1);
            mma16(ctx[1][2*j+1], pa[1], v2, v3);
        }
    }

    // ================= Normalize =================
    float inv[2][2], cden[2][2];
    #pragma unroll
    for (int mt = 0; mt < 2; mt++)
        #pragma unroll
        for (int hh = 0; hh < 2; hh++) {
            float d = den[mt][hh];
            d += __shfl_xor_sync(0xffffffffu, d, 1);
            d += __shfl_xor_sync(0xffffffffu, d, 2);
            inv[mt][hh]  = 1.0f / (d + 2.56e-10f);
            cden[mt][hh] = d * inv[mt][hh];
        }
    unsigned cf[2][4][4];
    #pragma unroll
    for (int mt = 0; mt < 2; mt++)
        #pragma unroll
        for (int kt = 0; kt < 4; kt++) {
            cf[mt][kt][0] = pack2(ctx[mt][2*kt].x * inv[mt][0],   ctx[mt][2*kt].y * inv[mt][0]);
            cf[mt][kt][1] = pack2(ctx[mt][2*kt].z * inv[mt][1],   ctx[mt][2*kt].w * inv[mt][1]);
            cf[mt][kt][2] = pack2(ctx[mt][2*kt+1].x * inv[mt][0], ctx[mt][2*kt+1].y * inv[mt][0]);
            cf[mt][kt][3] = pack2(ctx[mt][2*kt+1].z * inv[mt][1], ctx[mt][2*kt+1].w * inv[mt][1]);
        }

    // ================= Y = U' * W2^T =================
    float4 y[2][8];
    #pragma unroll
    for (int mt = 0; mt < 2; mt++)
        #pragma unroll
        for (int nt = 0; nt < 8; nt++) y[mt][nt] = make_float4(0.f, 0.f, 0.f, 0.f);
    #pragma unroll
    for (int kt = 0; kt < 4; kt++)
        #pragma unroll
        for (int j = 0; j < 4; j++) {
            unsigned b0, b1, b2, b3;
            ldsm4(b0, b1, b2, b3, &sW2[(16 * j + lro) * WS + 16 * kt + lco]);
            mma16(y[0][2*j],   cf[0][kt], b0, b1);
            mma16(y[0][2*j+1], cf[0][kt], b2, b3);
            mma16(y[1][2*j],   cf[1][kt], b0, b1);
            mma16(y[1][2*j+1], cf[1][kt], b2, b3);
        }

    // ================= Epilogue =================
    #pragma unroll
    for (int mt = 0; mt < 2; mt++) {
        const int rA = R0 + 16 * mt + g, rB = rA + 8;
        const float c0 = cden[mt][0], c1 = cden[mt][1];
        float s0 = 0.f, s1 = 0.f, q0 = 0.f, q1 = 0.f;
        #pragma unroll
        for (int nt = 0; nt < 8; nt++) {
            int c = 8 * nt + 2 * t;
            float2 wv = *(const float2*)&swbv[c];
            float2 bb = __ldg((const float2*)&bo[c]);
            float2 x0 = *(const float2*)&xg[rA * 64 + c];
            float2 x1 = *(const float2*)&xg[rB * 64 + c];
            y[mt][nt].x += c0 * wv.x + bb.x + x0.x;
            y[mt][nt].y += c0 * wv.y + bb.y + x0.y;
            y[mt][nt].z += c1 * wv.x + bb.x + x1.x;
            y[mt][nt].w += c1 * wv.y + bb.y + x1.y;
            s0 += y[mt][nt].x + y[mt][nt].y;  q0 += y[mt][nt].x * y[mt][nt].x + y[mt][nt].y * y[mt][nt].y;
            s1 += y[mt][nt].z + y[mt][nt].w;  q1 += y[mt][nt].z * y[mt][nt].z + y[mt][nt].w * y[mt][nt].w;
        }
        s0 += __shfl_xor_sync(0xffffffffu, s0, 1); s0 += __shfl_xor_sync(0xffffffffu, s0, 2);
        q0 += __shfl_xor_sync(0xffffffffu, q0, 1); q0 += __shfl_xor_sync(0xffffffffu, q0, 2);
        s1 += __shfl_xor_sync(0xffffffffu, s1, 1); s1 += __shfl_xor_sync(0xffffffffu, s1, 2);
        q1 += __shfl_xor_sync(0xffffffffu, q1, 1); q1 += __shfl_xor_sync(0xffffffffu, q1, 2);
        float mu0 = s0 * (1.f / 64.f), mu1 = s1 * (1.f / 64.f);
        float rs0 = rsqrtf(q0 * (1.f / 64.f) - mu0 * mu0 + 1e-5f);
        float rs1 = rsqrtf(q1 * (1.f / 64.f) - mu1 * mu1 + 1e-5f);
        #pragma unroll
        for (int nt = 0; nt < 8; nt++) {
            int c = 8 * nt + 2 * t;
            float2 gg = __ldg((const float2*)&lng[c]);
            float2 bb = __ldg((const float2*)&lnb[c]);
            *(float2*)&og[rA * 64 + c] = make_float2((y[mt][nt].x - mu0) * rs0 * gg.x + bb.x,
                                                     (y[mt][nt].y - mu0) * rs0 * gg.y + bb.y);
            *(float2*)&og[rB * 64 + c] = make_float2((y[mt][nt].z - mu1) * rs1 * gg.x + bb.x,
                                                     (y[mt][nt].w - mu1) * rs1 * gg.y + bb.y);
        }
    }
}

extern "C" void kernel_launch(void* const* d_in, const int* in_sizes, int n_in,
                              void* d_out, int out_size)
{
    const float* x   = (const float*)d_in[1];
    const float* Wq  = (const float*)d_in[2];
    const float* bq  = (const float*)d_in[3];
    const float* Wk  = (const float*)d_in[4];
    const float* bk  = (const float*)d_in[5];
    const float* Wv  = (const float*)d_in[6];
    const float* bv  = (const float*)d_in[7];
    const float* Wo  = (const float*)d_in[8];
    const float* bo  = (const float*)d_in[9];
    const float* lng = (const float*)d_in[10];
    const float* lnb = (const float*)d_in[11];
    float* out = (float*)d_out;

    int tiles = in_sizes[1] / (256 * 64);   // 1024
    int grid  = tiles * 2;                  // 2 CTAs per tile

    // smem: 46080 halves + 705 floats = 92160 + 2820 = 94980 -> 94984 B
    size_t smem = (size_t)OEND * sizeof(__half) + 705 * sizeof(float) + 4;
    cudaFuncSetAttribute(pair_attn_v13,
                         cudaFuncAttributeMaxDynamicSharedMemorySize, (int)smem);

    pair_attn_v13<<<grid, 128, smem>>>(x, Wq, bq, Wk, bk, Wv, bv, Wo, bo,
                                       lng, lnb, out);
}

// round 17
// speedup vs baseline: 1.2406x; 1.2406x over previous
#include <cuda_runtime.h>
#include <cuda_fp16.h>

// B=4, N=256, M=256, D=64. One CTA per (b,i) tile; SINGLE kernel.
// 512 threads = 16 warps; warp w owns rows [16w,16w+16).
// Fused algebra (in-CTA): Wg[n][k]=(Wk^T Wq)[k][n]/8, W2[n][k]=(Wo Wv)[n][k],
//   h1=Wk^T bq/8 (Wg row 64), h2=Wq^T bk/8 (row 65), wbv=Wo bv, s0=bk.bq/8.
// G = X*Wg (+extra n-tile -> t2,t3) ; S = G*X^T + t2_a + t3_c ; P = relu(S)
// U = P*X where the B-fragments come from MOVMATRIX of the S-phase q fragments
//   (no smem re-read: v0=movm(q0), v1=movm(q2), v2=movm(q1), v3=movm(q3))
// out = U*inv*W2^T + cden*wbv + bo + x ; LayerNorm.

#define QS 72
#define WS 72
#define OX   0
#define OWQ  18432
#define OWK  23040
#define OWV  27648
#define OWO  32256
#define OWG  36864   // 80 rows: 0-63 Wg, 64 h1, 65 h2, 66-79 zero
#define OW2  42624
#define OEND 47232

__device__ __forceinline__ void mma16(float4& d, const unsigned a[4], unsigned b0, unsigned b1) {
    asm("mma.sync.aligned.m16n8k16.row.col.f32.f16.f16.f32 "
        "{%0,%1,%2,%3},{%4,%5,%6,%7},{%8,%9},{%0,%1,%2,%3};"
        : "+f"(d.x), "+f"(d.y), "+f"(d.z), "+f"(d.w)
        : "r"(a[0]), "r"(a[1]), "r"(a[2]), "r"(a[3]), "r"(b0), "r"(b1));
}
__device__ __forceinline__ void ldsm4(unsigned& r0, unsigned& r1, unsigned& r2, unsigned& r3,
                                      const __half* p) {
    unsigned a = (unsigned)__cvta_generic_to_shared(p);
    asm volatile("ldmatrix.sync.aligned.m8n8.x4.shared.b16 {%0,%1,%2,%3},[%4];"
                 : "=r"(r0), "=r"(r1), "=r"(r2), "=r"(r3) : "r"(a));
}
__device__ __forceinline__ void ldsm4t(unsigned& r0, unsigned& r1, unsigned& r2, unsigned& r3,
                                       const __half* p) {
    unsigned a = (unsigned)__cvta_generic_to_shared(p);
    asm volatile("ldmatrix.sync.aligned.m8n8.x4.trans.shared.b16 {%0,%1,%2,%3},[%4];"
                 : "=r"(r0), "=r"(r1), "=r"(r2), "=r"(r3) : "r"(a));
}
__device__ __forceinline__ unsigned movm(unsigned a) {
    unsigned d;
    asm("movmatrix.sync.aligned.m8n8.trans.b16 %0, %1;" : "=r"(d) : "r"(a));
    return d;
}
__device__ __forceinline__ unsigned pack2(float lo, float hi) {
    __half2 h = __floats2half2_rn(lo, hi);
    return *reinterpret_cast<unsigned*>(&h);
}
// 512-thread weight stage: thread -> row tid/8, 8-col run.
__device__ __forceinline__ void stageW512(const float* __restrict__ W, __half* dst, int tid) {
    const int f  = tid >> 3;
    const int e0 = (tid & 7) * 8;
    float4 p0 = *(const float4*)(W + f * 64 + e0);
    float4 p1 = *(const float4*)(W + f * 64 + e0 + 4);
    unsigned u[4] = {pack2(p0.x, p0.y), pack2(p0.z, p0.w),
                     pack2(p1.x, p1.y), pack2(p1.z, p1.w)};
    *(uint4*)&dst[f * WS + e0] = *(uint4*)u;
}

__global__ void __launch_bounds__(512, 1)
pair_attn_v14(const float* __restrict__ x_all,
              const float* __restrict__ Wq, const float* __restrict__ bq,
              const float* __restrict__ Wk, const float* __restrict__ bk,
              const float* __restrict__ Wv, const float* __restrict__ bv,
              const float* __restrict__ Wo, const float* __restrict__ bo,
              const float* __restrict__ lng, const float* __restrict__ lnb,
              float* __restrict__ out_all)
{
    extern __shared__ __half sm[];
    __half* sX  = sm + OX;
    __half* sWg = sm + OWG;
    __half* sW2 = sm + OW2;
    float*  fs   = (float*)(sm + OEND);
    float*  t3s  = fs;          // [256]
    float*  swbv = fs + 256;    // [64]
    float*  s0s  = fs + 320;    // [1]

    const int tid  = threadIdx.x;
    const int lane = tid & 31;
    const int wrp  = tid >> 5;          // 0..15
    const int g    = lane >> 2;
    const int t    = lane & 3;
    const int R0   = wrp * 16;
    const int lro  = ((lane >> 4) & 1) * 8 + (lane & 7);  // non-trans B / trans A
    const int lco  = ((lane >> 3) & 1) * 8;
    const int vro  = ((lane >> 3) & 1) * 8 + (lane & 7);  // trans B
    const int vco  = ((lane >> 4) & 1) * 8;
    const int aro  = lane & 15;                           // non-trans A
    const int aco  = ((lane >> 4) & 1) * 8;

    const float* xg = x_all   + (size_t)blockIdx.x * 16384;
    float*       og = out_all + (size_t)blockIdx.x * 16384;

    // ================= Phase A: staging =================
    {
        const float4* x4 = (const float4*)xg;
        #pragma unroll
        for (int i = 0; i < 8; i++) {
            int idx = tid + 512 * i;
            int row = idx >> 4, c4 = idx & 15;
            float4 v = x4[idx];
            *(uint2*)&sX[row * QS + c4 * 4] = make_uint2(pack2(v.x, v.y), pack2(v.z, v.w));
        }
        stageW512(Wq, sm + OWQ, tid);
        stageW512(Wk, sm + OWK, tid);
        stageW512(Wv, sm + OWV, tid);
        stageW512(Wo, sm + OWO, tid);
        unsigned* wz = (unsigned*)(sWg + 66 * WS);
        for (int i = tid; i < 504; i += 512) wz[i] = 0;
        if (tid < 64) {
            float a0 = 0.f, a1 = 0.f, a2 = 0.f, a3 = 0.f;
            #pragma unroll
            for (int j = 0; j < 64; j += 4) {
                a0 = fmaf(__ldg(bq + j + 0), __ldg(Wk + (j + 0) * 64 + tid), a0);
                a1 = fmaf(__ldg(bq + j + 1), __ldg(Wk + (j + 1) * 64 + tid), a1);
                a2 = fmaf(__ldg(bq + j + 2), __ldg(Wk + (j + 2) * 64 + tid), a2);
                a3 = fmaf(__ldg(bq + j + 3), __ldg(Wk + (j + 3) * 64 + tid), a3);
            }
            sWg[64 * WS + tid] = __float2half_rn(((a0 + a1) + (a2 + a3)) * 0.125f);
        } else if (tid < 128) {
            int i = tid - 64;
            float a0 = 0.f, a1 = 0.f, a2 = 0.f, a3 = 0.f;
            #pragma unroll
            for (int j = 0; j < 64; j += 4) {
                a0 = fmaf(__ldg(bk + j + 0), __ldg(Wq + (j + 0) * 64 + i), a0);
                a1 = fmaf(__ldg(bk + j + 1), __ldg(Wq + (j + 1) * 64 + i), a1);
                a2 = fmaf(__ldg(bk + j + 2), __ldg(Wq + (j + 2) * 64 + i), a2);
                a3 = fmaf(__ldg(bk + j + 3), __ldg(Wq + (j + 3) * 64 + i), a3);
            }
            sWg[65 * WS + i] = __float2half_rn(((a0 + a1) + (a2 + a3)) * 0.125f);
        } else if (tid < 192) {
            int i = tid - 128;
            float a = 0.f;
            #pragma unroll
            for (int j = 0; j < 64; j += 4) {
                float4 w = __ldg((const float4*)&Wo[i * 64 + j]);
                float4 b = __ldg((const float4*)&bv[j]);
                a += w.x * b.x + w.y * b.y + w.z * b.z + w.w * b.w;
            }
            swbv[i] = a;
        } else if (tid == 192) {
            float s = 0.f;
            #pragma unroll
            for (int j = 0; j < 64; j++) s = fmaf(__ldg(bk + j), __ldg(bq + j), s);
            s0s[0] = s * 0.125f;
        }
    }
    __syncthreads();   // B1

    // ================= Phase B: Wg / W2 via MMA (warps 0-7) =================
    if (wrp < 4) {
        const int m0 = 16 * wrp;
        float4 dW[8];
        #pragma unroll
        for (int nt = 0; nt < 8; nt++) dW[nt] = make_float4(0.f, 0.f, 0.f, 0.f);
        #pragma unroll
        for (int kt = 0; kt < 4; kt++) {
            unsigned a[4];
            ldsm4t(a[0], a[1], a[2], a[3], &sm[OWQ + (16 * kt + lro) * WS + m0 + lco]);
            #pragma unroll
            for (int jj = 0; jj < 4; jj++) {
                unsigned b0, b1, b2, b3;
                ldsm4t(b0, b1, b2, b3, &sm[OWK + (16 * kt + vro) * WS + 16 * jj + vco]);
                mma16(dW[2*jj],   a, b0, b1);
                mma16(dW[2*jj+1], a, b2, b3);
            }
        }
        #pragma unroll
        for (int nt = 0; nt < 8; nt++) {
            *(unsigned*)&sWg[(m0 + g) * WS + 8 * nt + 2 * t]     = pack2(dW[nt].x * 0.125f, dW[nt].y * 0.125f);
            *(unsigned*)&sWg[(m0 + 8 + g) * WS + 8 * nt + 2 * t] = pack2(dW[nt].z * 0.125f, dW[nt].w * 0.125f);
        }
    } else if (wrp < 8) {
        const int m0 = 16 * (wrp - 4);
        float4 dW[8];
        #pragma unroll
        for (int nt = 0; nt < 8; nt++) dW[nt] = make_float4(0.f, 0.f, 0.f, 0.f);
        #pragma unroll
        for (int kt = 0; kt < 4; kt++) {
            unsigned a[4];
            ldsm4(a[0], a[1], a[2], a[3], &sm[OWO + (m0 + aro) * WS + 16 * kt + aco]);
            #pragma unroll
            for (int jj = 0; jj < 4; jj++) {
                unsigned b0, b1, b2, b3;
                ldsm4t(b0, b1, b2, b3, &sm[OWV + (16 * kt + vro) * WS + 16 * jj + vco]);
                mma16(dW[2*jj],   a, b0, b1);
                mma16(dW[2*jj+1], a, b2, b3);
            }
        }
        #pragma unroll
        for (int nt = 0; nt < 8; nt++) {
            *(unsigned*)&sW2[(m0 + g) * WS + 8 * nt + 2 * t]     = pack2(dW[nt].x, dW[nt].y);
            *(unsigned*)&sW2[(m0 + 8 + g) * WS + 8 * nt + 2 * t] = pack2(dW[nt].z, dW[nt].w);
        }
    }
    __syncthreads();   // B2

    // ================= Phase C: G = X*Wg (+t2/t3 tile) =================
    unsigned ga[4][4];
    float t2A, t2B;
    {
        unsigned xa[4][4];
        #pragma unroll
        for (int kt = 0; kt < 4; kt++)
            ldsm4(xa[kt][0], xa[kt][1], xa[kt][2], xa[kt][3],
                  &sX[(R0 + aro) * QS + 16 * kt + aco]);
        float4 d[8], dE;
        #pragma unroll
        for (int nt = 0; nt < 8; nt++) d[nt] = make_float4(0.f, 0.f, 0.f, 0.f);
        dE = make_float4(0.f, 0.f, 0.f, 0.f);
        #pragma unroll
        for (int kt = 0; kt < 4; kt++) {
            #pragma unroll
            for (int j = 0; j < 4; j++) {
                unsigned b0, b1, b2, b3;
                ldsm4(b0, b1, b2, b3, &sWg[(16 * j + lro) * WS + 16 * kt + lco]);
                mma16(d[2*j],   xa[kt], b0, b1);
                mma16(d[2*j+1], xa[kt], b2, b3);
            }
            unsigned e0, e1, e2, e3;
            ldsm4(e0, e1, e2, e3, &sWg[(64 + lro) * WS + 16 * kt + lco]);
            mma16(dE, xa[kt], e0, e1);
        }
        #pragma unroll
        for (int kt = 0; kt < 4; kt++) {
            ga[kt][0] = pack2(d[2*kt].x,   d[2*kt].y);
            ga[kt][1] = pack2(d[2*kt].z,   d[2*kt].w);
            ga[kt][2] = pack2(d[2*kt+1].x, d[2*kt+1].y);
            ga[kt][3] = pack2(d[2*kt+1].z, d[2*kt+1].w);
        }
        const float s0v = s0s[0];
        if (t == 0) {
            t3s[R0 + g]     = dE.y + s0v;
            t3s[R0 + 8 + g] = dE.w + s0v;
        }
        t2A = __shfl_sync(0xffffffffu, dE.x, lane & ~3);
        t2B = __shfl_sync(0xffffffffu, dE.z, lane & ~3);
    }
    __syncthreads();   // B3

    // ================= Mainloop (U B-operands via movmatrix, no smem re-read) ========
    float4 ctx[8];
    #pragma unroll
    for (int nt = 0; nt < 8; nt++) ctx[nt] = make_float4(0.f, 0.f, 0.f, 0.f);
    float den0 = 0.f, den1 = 0.f;

    #pragma unroll 2
    for (int cb = 0; cb < 16; cb++) {
        const float2 tcA = *(const float2*)&t3s[16 * cb + 2 * t];
        const float2 tcB = *(const float2*)&t3s[16 * cb + 8 + 2 * t];
        unsigned qf[4][4];
        float4 s0 = make_float4(0.f, 0.f, 0.f, 0.f), s1 = s0;
        #pragma unroll
        for (int kt = 0; kt < 4; kt++) {
            ldsm4(qf[kt][0], qf[kt][1], qf[kt][2], qf[kt][3],
                  &sX[(16 * cb + lro) * QS + 16 * kt + lco]);
            mma16(s0, ga[kt], qf[kt][0], qf[kt][1]);
            mma16(s1, ga[kt], qf[kt][2], qf[kt][3]);
        }
        float ex = fmaxf(s0.x + t2A + tcA.x, 0.f), ey = fmaxf(s0.y + t2A + tcA.y, 0.f);
        float ez = fmaxf(s0.z + t2B + tcA.x, 0.f), ew = fmaxf(s0.w + t2B + tcA.y, 0.f);
        float ox = fmaxf(s1.x + t2A + tcB.x, 0.f), oy = fmaxf(s1.y + t2A + tcB.y, 0.f);
        float oz = fmaxf(s1.z + t2B + tcB.x, 0.f), ow = fmaxf(s1.w + t2B + tcB.y, 0.f);
        den0 += (ex + ey) + (ox + oy);
        den1 += (ez + ew) + (oz + ow);
        unsigned pa[4];
        pa[0] = pack2(ex, ey); pa[1] = pack2(ez, ew);
        pa[2] = pack2(ox, oy); pa[3] = pack2(oz, ow);
        #pragma unroll
        for (int j = 0; j < 4; j++) {
            // transpose of S-phase fragments: v0=T(q0), v1=T(q2), v2=T(q1), v3=T(q3)
            unsigned v0 = movm(qf[j][0]);
            unsigned v1 = movm(qf[j][2]);
            unsigned v2 = movm(qf[j][1]);
            unsigned v3 = movm(qf[j][3]);
            mma16(ctx[2*j],   pa, v0, v1);
            mma16(ctx[2*j+1], pa, v2, v3);
        }
    }

    // ================= Normalize =================
    den0 += __shfl_xor_sync(0xffffffffu, den0, 1);
    den0 += __shfl_xor_sync(0xffffffffu, den0, 2);
    den1 += __shfl_xor_sync(0xffffffffu, den1, 1);
    den1 += __shfl_xor_sync(0xffffffffu, den1, 2);
    const float inv0 = 1.0f / (den0 + 2.56e-10f), inv1 = 1.0f / (den1 + 2.56e-10f);
    const float cd0 = den0 * inv0, cd1 = den1 * inv1;
    unsigned cf[4][4];
    #pragma unroll
    for (int kt = 0; kt < 4; kt++) {
        cf[kt][0] = pack2(ctx[2*kt].x * inv0,   ctx[2*kt].y * inv0);
        cf[kt][1] = pack2(ctx[2*kt].z * inv1,   ctx[2*kt].w * inv1);
        cf[kt][2] = pack2(ctx[2*kt+1].x * inv0, ctx[2*kt+1].y * inv0);
        cf[kt][3] = pack2(ctx[2*kt+1].z * inv1, ctx[2*kt+1].w * inv1);
    }

    // ================= Y = U' * W2^T =================
    float4 y[8];
    #pragma unroll
    for (int nt = 0; nt < 8; nt++) y[nt] = make_float4(0.f, 0.f, 0.f, 0.f);
    #pragma unroll
    for (int kt = 0; kt < 4; kt++)
        #pragma unroll
        for (int j = 0; j < 4; j++) {
            unsigned b0, b1, b2, b3;
            ldsm4(b0, b1, b2, b3, &sW2[(16 * j + lro) * WS + 16 * kt + lco]);
            mma16(y[2*j],   cf[kt], b0, b1);
            mma16(y[2*j+1], cf[kt], b2, b3);
        }

    // ================= Epilogue =================
    {
        const int rA = R0 + g, rB = rA + 8;
        float s0 = 0.f, s1 = 0.f, q0 = 0.f, q1 = 0.f;
        #pragma unroll
        for (int nt = 0; nt < 8; nt++) {
            int c = 8 * nt + 2 * t;
            float2 wv = *(const float2*)&swbv[c];
            float2 bb = __ldg((const float2*)&bo[c]);
            float2 x0 = *(const float2*)&xg[rA * 64 + c];
            float2 x1 = *(const float2*)&xg[rB * 64 + c];
            y[nt].x += cd0 * wv.x + bb.x + x0.x;
            y[nt].y += cd0 * wv.y + bb.y + x0.y;
            y[nt].z += cd1 * wv.x + bb.x + x1.x;
            y[nt].w += cd1 * wv.y + bb.y + x1.y;
            s0 += y[nt].x + y[nt].y;  q0 += y[nt].x * y[nt].x + y[nt].y * y[nt].y;
            s1 += y[nt].z + y[nt].w;  q1 += y[nt].z * y[nt].z + y[nt].w * y[nt].w;
        }
        s0 += __shfl_xor_sync(0xffffffffu, s0, 1); s0 += __shfl_xor_sync(0xffffffffu, s0, 2);
        q0 += __shfl_xor_sync(0xffffffffu, q0, 1); q0 += __shfl_xor_sync(0xffffffffu, q0, 2);
        s1 += __shfl_xor_sync(0xffffffffu, s1, 1); s1 += __shfl_xor_sync(0xffffffffu, s1, 2);
        q1 += __shfl_xor_sync(0xffffffffu, q1, 1); q1 += __shfl_xor_sync(0xffffffffu, q1, 2);
        float mu0 = s0 * (1.f / 64.f), mu1 = s1 * (1.f / 64.f);
        float rs0 = rsqrtf(q0 * (1.f / 64.f) - mu0 * mu0 + 1e-5f);
        float rs1 = rsqrtf(q1 * (1.f / 64.f) - mu1 * mu1 + 1e-5f);
        #pragma unroll
        for (int nt = 0; nt < 8; nt++) {
            int c = 8 * nt + 2 * t;
            float2 gg = __ldg((const float2*)&lng[c]);
            float2 bb = __ldg((const float2*)&lnb[c]);
            *(float2*)&og[rA * 64 + c] = make_float2((y[nt].x - mu0) * rs0 * gg.x + bb.x,
                                                     (y[nt].y - mu0) * rs0 * gg.y + bb.y);
            *(float2*)&og[rB * 64 + c] = make_float2((y[nt].z - mu1) * rs1 * gg.x + bb.x,
                                                     (y[nt].w - mu1) * rs1 * gg.y + bb.y);
        }
    }
}

extern "C" void kernel_launch(void* const* d_in, const int* in_sizes, int n_in,
                              void* d_out, int out_size)
{
    const float* x   = (const float*)d_in[1];
    const float* Wq  = (const float*)d_in[2];
    const float* bq  = (const float*)d_in[3];
    const float* Wk  = (const float*)d_in[4];
    const float* bk  = (const float*)d_in[5];
    const float* Wv  = (const float*)d_in[6];
    const float* bv  = (const float*)d_in[7];
    const float* Wo  = (const float*)d_in[8];
    const float* bo  = (const float*)d_in[9];
    const float* lng = (const float*)d_in[10];
    const float* lnb = (const float*)d_in[11];
    float* out = (float*)d_out;

    int tiles = in_sizes[1] / (256 * 64);   // B*N = 1024

    size_t smem = (size_t)OEND * sizeof(__half) + 321 * sizeof(float) + 12;
    cudaFuncSetAttribute(pair_attn_v14,
                         cudaFuncAttributeMaxDynamicSharedMemorySize, (int)smem);

    pair_attn_v14<<<tiles, 512, smem>>>(x, Wq, bq, Wk, bk, Wv, bv, Wo, bo,
                                        lng, lnb, out);
}